// round 15
// baseline (speedup 1.0000x reference)
#include <cuda_runtime.h>
#include <cuda_bf16.h>

#define Bn 8
#define Sn 512
#define Kn 16
#define Rr 8            // output rows per block
#define SW (Sn + 8)     // padded row: idx 0..3 zero, data 4..515, idx 516..519 zero
#define EMPTY_DIST 362.1f
#define FAR_COORD 1.0e18f

// Persistent scratch (no allocations allowed). Starts zeroed (.bss);
// the last main block resets counters after use -> deterministic replays.
__device__ float    g_py[Bn][Kn];
__device__ float    g_px[Bn][Kn];
__device__ int      g_cnt[Bn];
__device__ unsigned g_maxbits[Bn];
__device__ double   g_numer[Bn];
__device__ double   g_gradsum;
__device__ unsigned g_done;

// ---------------------------------------------------------------------------
// Kernel 1: collect nonzero label pixels. Wide grid: (slices, Bn).
// ---------------------------------------------------------------------------
#define CSLICES 64
__global__ __launch_bounds__(256) void collect_kernel(const float* __restrict__ pt) {
    const int b = blockIdx.y;
    const int slice = blockIdx.x;
    const int n4_per_slice = (Sn * Sn / 4) / CSLICES;      // 1024 float4
    const float4* p = (const float4*)(pt + (size_t)b * Sn * Sn) + slice * n4_per_slice;
    for (int i = threadIdx.x; i < n4_per_slice; i += 256) {
        float4 v = p[i];
        if (v.x != 0.f || v.y != 0.f || v.z != 0.f || v.w != 0.f) {
            float vv[4] = {v.x, v.y, v.z, v.w};
            int base_idx = (slice * n4_per_slice + i) * 4;
            #pragma unroll
            for (int j = 0; j < 4; j++) {
                if (vv[j] != 0.f) {
                    int idx = base_idx + j;
                    int slot = atomicAdd(&g_cnt[b], 1);
                    if (slot < Kn) {
                        g_py[b][slot] = (float)(idx / Sn);
                        g_px[b][slot] = (float)(idx % Sn);
                    }
                }
            }
        }
    }
}

// ---------------------------------------------------------------------------
// Kernel 2: fused distance + sobel + reductions + finalize.
// grid (Sn/Rr, Bn), 512 threads, 3 blocks/SM. float4 staging path.
// Order: LDG.128 loads -> cull+distance mins (no smem dep) -> sync ->
//        epilogue (s_pred) -> branch-free sobel -> reduce.
// ---------------------------------------------------------------------------
__global__ __launch_bounds__(512, 3) void main_kernel(const float* __restrict__ pred,
                                                      const float* __restrict__ ori,
                                                      float* __restrict__ out) {
    __shared__ float s_img[Rr + 2][SW];     // idx 0..3 and 516..519 are zero
    __shared__ float s_pred[Rr][Sn];        // pred staged for the epilogue
    __shared__ float sh_s[16], sh_g[16], sh_m[16];

    const int y0 = blockIdx.x * Rr;
    const int b  = blockIdx.y;
    const int x  = threadIdx.x;
    const int lane = x & 31;

    const float* __restrict__ pb = pred + b * (Sn * Sn);
    const float* __restrict__ ob = ori  + b * (Sn * Sn);

    // point coords in registers (lane<16), broadcast later via shfl. L2-hot.
    int cload = 0;
    float pxv = FAR_COORD, pyv = FAR_COORD;
    if (lane == 0) cload = g_cnt[b];
    const int cnt = min(__shfl_sync(0xffffffffu, cload, 0), Kn);
    if (lane < Kn) {
        if (lane < cnt) { pxv = g_px[b][lane]; pyv = g_py[b][lane]; }
    }

    // zero the 8 padding words per row (80 total)
    if (x < 80) {
        int row = x / 8, j = x & 7;
        s_img[row][(j < 4) ? j : (512 + j)] = 0.f;
    }

    // --- phase 1: cooperative float4 loads. 1280 float4-slots over 512 thr. ---
    #pragma unroll
    for (int i = 0; i < 3; i++) {
        int g = i * 512 + x;
        if (g < (Rr + 2) * (Sn / 4)) {              // 1280
            int row = g >> 7;                       // 0..9
            int c   = g & 127;                      // float4 index within row
            int yy  = y0 - 1 + row;
            float4 p4 = make_float4(0.f, 0.f, 0.f, 0.f);
            float4 v4 = make_float4(0.f, 0.f, 0.f, 0.f);
            if (yy >= 0 && yy < Sn) {
                const float4* pp = (const float4*)(pb + yy * Sn) + c;
                const float4* oo = (const float4*)(ob + yy * Sn) + c;
                p4 = __ldg(pp);
                float4 o4 = __ldg(oo);
                v4.x = p4.x * o4.x; v4.y = p4.y * o4.y;
                v4.z = p4.z * o4.z; v4.w = p4.w * o4.w;
            }
            *(float4*)&s_img[row][4 + 4 * c] = v4;
            if (row >= 1 && row <= Rr)
                *(float4*)&s_pred[row - 1][4 * c] = p4;
        }
    }

    const float fx  = (float)x;
    const float fy0 = (float)y0;

    // --- phase 2a: exact per-warp point culling (no smem dependency) ---
    unsigned keep;
    {
        const float x0f = (float)(x & ~31);
        const float x1f = x0f + 31.0f;
        const float y1f = fy0 + (float)(Rr - 1);
        float lb = 3.0e38f, ubi = 3.0e38f;
        if (lane < Kn) {
            float dxl = x0f - pxv, dxr = pxv - x1f;
            float dxm = fmaxf(0.f, fmaxf(dxl, dxr));
            float dxM = fmaxf(fabsf(dxl), fabsf(x1f - pxv));
            float dyl = fy0 - pyv, dyr = pyv - y1f;
            float dym = fmaxf(0.f, fmaxf(dyl, dyr));
            float dyM = fmaxf(fabsf(dyl), fabsf(y1f - pyv));
            lb  = fmaf(dxm, dxm, dym * dym);
            ubi = fmaf(dxM, dxM, dyM * dyM);
        }
        float ub = ubi;
        #pragma unroll
        for (int o = 16; o > 0; o >>= 1)
            ub = fminf(ub, __shfl_xor_sync(0xffffffffu, ub, o));
        keep = __ballot_sync(0xffffffffu, lb <= ub);
    }

    // --- phase 2b: distance mins (overlaps sibling warps' load latency) ---
    float m[Rr];
    #pragma unroll
    for (int r = 0; r < Rr; r++) m[r] = 3.0e38f;

    unsigned mask = keep;
    while (mask) {
        int i = __ffs(mask) - 1;
        mask &= mask - 1;
        float px_i = __shfl_sync(0xffffffffu, pxv, i);
        float py_i = __shfl_sync(0xffffffffu, pyv, i);
        float dxv = fx - px_i;
        float dy0 = fy0 - py_i;
        float c = fmaf(dy0, dy0, dxv * dxv);
        float e = dy0 + dy0;
        #pragma unroll
        for (int r = 0; r < Rr; r++)
            m[r] = fminf(m[r], fmaf((float)r, e, c));       // d2(r) = m + r^2 later
    }

    __syncthreads();        // s_img + s_pred complete

    // --- phase 2c: distance epilogue (pred from smem) ---
    float vsum = 0.f, vmax = 0.f;
    #pragma unroll
    for (int r = 0; r < Rr; r++) {
        float d2 = m[r] + (float)(r * r);
        float dist = (cnt > 0) ? sqrtf(d2) : EMPTY_DIST;
        float dd = fmaxf(dist - 1.0f, 0.f);
        vsum += s_pred[r][x] * dd;
        vmax = fmaxf(vmax, dd);
    }

    // --- phase 3: branch-free rolling-window sobel (indices shifted +3) ---
    float gsum = 0.f;
    const float xokf = (x >= 1 && x <= Sn - 2) ? 1.f : 0.f;

    float a0l = s_img[0][x + 3], a0c = s_img[0][x + 4], a0r = s_img[0][x + 5];
    float a1l = s_img[1][x + 3],                        a1r = s_img[1][x + 5];

    #pragma unroll
    for (int r = 0; r < Rr; r++) {
        const int y = y0 + r;
        float a2l = s_img[r + 2][x + 3], a2c = s_img[r + 2][x + 4], a2r = s_img[r + 2][x + 5];

        float t = a0c - a2c;     // n01 - n21
        float u = a1r - a1l;     // n12 - n10
        float p = a0r - a2l;     // n02 - n20
        float q = a0l - a2r;     // n00 - n22
        float g0 = fmaf(2.f, u, p - q);
        float g1 = fmaf(2.f, t, p + q);
        float g2 = fmaf(2.f, q, t - u);
        float g3 = fmaf(2.f, p, t + u);
        float gm = fmaxf(fmaxf(fabsf(g0), fabsf(g1)), fmaxf(fabsf(g2), fabsf(g3)));
        float maskf = (y >= 1 && y <= Sn - 2) ? xokf : 0.f;  // y part block-uniform
        gsum = fmaf(maskf, gm, gsum);

        a0l = a1l; a0c = s_img[r + 1][x + 4]; a0r = a1r;
        a1l = a2l;                            a1r = a2r;
    }

    // --- block reduction: sum(vsum), sum(gsum), max(vmax) ---
    #pragma unroll
    for (int o = 16; o > 0; o >>= 1) {
        vsum += __shfl_down_sync(0xffffffffu, vsum, o);
        gsum += __shfl_down_sync(0xffffffffu, gsum, o);
        vmax = fmaxf(vmax, __shfl_down_sync(0xffffffffu, vmax, o));
    }
    const int wid = x >> 5;
    if (lane == 0) { sh_s[wid] = vsum; sh_g[wid] = gsum; sh_m[wid] = vmax; }
    __syncthreads();
    if (wid == 0) {
        vsum = (lane < 16) ? sh_s[lane] : 0.f;
        gsum = (lane < 16) ? sh_g[lane] : 0.f;
        vmax = (lane < 16) ? sh_m[lane] : 0.f;
        #pragma unroll
        for (int o = 8; o > 0; o >>= 1) {
            vsum += __shfl_down_sync(0xffffffffu, vsum, o);
            gsum += __shfl_down_sync(0xffffffffu, gsum, o);
            vmax = fmaxf(vmax, __shfl_down_sync(0xffffffffu, vmax, o));
        }
        if (lane == 0) {
            atomicAdd(&g_numer[b], (double)vsum);
            atomicAdd(&g_gradsum, (double)gsum);
            atomicMax(&g_maxbits[b], __float_as_uint(vmax));

            __threadfence();
            unsigned ticket = atomicAdd(&g_done, 1u);
            const unsigned total = (Sn / Rr) * Bn;
            if (ticket == total - 1u) {
                double acc = 0.0;
                #pragma unroll
                for (int bb = 0; bb < Bn; bb++) {
                    float mx = __uint_as_float(g_maxbits[bb]);
                    acc += g_numer[bb] / (double)mx;
                    g_numer[bb] = 0.0;
                    g_maxbits[bb] = 0u;
                    g_cnt[bb] = 0;
                }
                const double denom = (double)Sn * (double)Sn * (double)Bn;
                out[0] = (float)(acc / denom);
                out[1] = (float)(g_gradsum / denom);
                g_gradsum = 0.0;
                g_done = 0u;
                __threadfence();
            }
        }
    }
}

extern "C" void kernel_launch(void* const* d_in, const int* in_sizes, int n_in,
                              void* d_out, int out_size) {
    const float* pred = (const float*)d_in[0];
    const float* ptl  = (const float*)d_in[1];
    const float* ori  = (const float*)d_in[2];
    float* out = (float*)d_out;

    collect_kernel<<<dim3(CSLICES, Bn), 256>>>(ptl);
    main_kernel<<<dim3(Sn / Rr, Bn), 512>>>(pred, ori, out);
}